// round 1
// baseline (speedup 1.0000x reference)
#include <cuda_runtime.h>

#define FULL_MASK 0xFFFFFFFFu

// In-warp 128-point Fast Walsh-Hadamard Transform.
// Element layout: index = lane*4 + j  (j = component of float4).
// Butterfly stages over index bits: bit0,bit1 in-register; bits2..6 via shfl.
// Sylvester Hadamard is exactly what the bit-butterfly computes (H symmetric).
__device__ __forceinline__ float4 fwht128(float4 v, int lane) {
    // stride-1 (index bit 0): pairs (0,1),(2,3)
    float a = v.x + v.y;
    float b = v.x - v.y;
    float c = v.z + v.w;
    float d = v.z - v.w;
    // stride-2 (index bit 1): pairs (0,2),(1,3)
    v.x = a + c;
    v.y = b + d;
    v.z = a - c;
    v.w = b - d;
    // strides 4..64 (index bits 2..6) = lane bits 0..4
#pragma unroll
    for (int mask = 1; mask <= 16; mask <<= 1) {
        float ox = __shfl_xor_sync(FULL_MASK, v.x, mask);
        float oy = __shfl_xor_sync(FULL_MASK, v.y, mask);
        float oz = __shfl_xor_sync(FULL_MASK, v.z, mask);
        float ow = __shfl_xor_sync(FULL_MASK, v.w, mask);
        if (lane & mask) {
            v.x = ox - v.x;
            v.y = oy - v.y;
            v.z = oz - v.z;
            v.w = ow - v.w;
        } else {
            v.x = v.x + ox;
            v.y = v.y + oy;
            v.z = v.z + oz;
            v.w = v.w + ow;
        }
    }
    return v;
}

// One warp handles one row-index: the q row (rotate) and the k row
// (rotate + 4-bit symmetric fake-quant). Rows are 128 contiguous floats;
// each lane owns a float4 => perfectly coalesced 512B per row access.
__global__ void __launch_bounds__(256)
qk_rot_quant_kernel(const float4* __restrict__ qin,
                    const float4* __restrict__ kin,
                    float4* __restrict__ qout,
                    float4* __restrict__ kout,
                    int nrows) {
    const int gwarp = (blockIdx.x * blockDim.x + threadIdx.x) >> 5;
    const int lane = threadIdx.x & 31;
    if (gwarp >= nrows) return;

    const float s = 0.088388347648318447f;  // 1/sqrt(128)
    const long long idx = (long long)gwarp * 32 + lane;

    // ---- issue both loads up front (MLP=2 per thread) ----
    float4 q = qin[idx];
    float4 k = kin[idx];

    // ---- Q: rotate + scale ----
    q = fwht128(q, lane);
    q.x *= s; q.y *= s; q.z *= s; q.w *= s;
    qout[idx] = q;

    // ---- K: rotate + scale ----
    k = fwht128(k, lane);
    k.x *= s; k.y *= s; k.z *= s; k.w *= s;

    // row amax over |k| (4 local + 5-step warp reduce)
    float amax = fmaxf(fmaxf(fabsf(k.x), fabsf(k.y)),
                       fmaxf(fabsf(k.z), fabsf(k.w)));
#pragma unroll
    for (int mask = 16; mask >= 1; mask >>= 1)
        amax = fmaxf(amax, __shfl_xor_sync(FULL_MASK, amax, mask));
    if (amax == 0.0f) amax = 1.0f;  // xmax==0 -> 1.0 (reference semantics)

    // qscale = xmax / MAXQ (single rounding, matches reference)
    const float qscale = amax / 7.0f;

    // round-half-even (rintf) like jnp.round, clip to [-8, 7], rescale
    k.x = fminf(fmaxf(rintf(k.x / qscale), -8.0f), 7.0f) * qscale;
    k.y = fminf(fmaxf(rintf(k.y / qscale), -8.0f), 7.0f) * qscale;
    k.z = fminf(fmaxf(rintf(k.z / qscale), -8.0f), 7.0f) * qscale;
    k.w = fminf(fmaxf(rintf(k.w / qscale), -8.0f), 7.0f) * qscale;

    kout[idx] = k;
}

extern "C" void kernel_launch(void* const* d_in, const int* in_sizes, int n_in,
                              void* d_out, int out_size) {
    const float4* qin = (const float4*)d_in[0];
    const float4* kin = (const float4*)d_in[1];

    const int n_elems = in_sizes[0];       // 2*32*4096*128 = 33554432
    const int nrows = n_elems / 128;       // 262144

    // output: q (n_elems floats) then k (n_elems floats)
    float4* qout = (float4*)d_out;
    float4* kout = (float4*)d_out + (size_t)n_elems / 4;

    const int threads = 256;               // 8 warps = 8 rows per block
    const int rows_per_block = threads / 32;
    const int blocks = (nrows + rows_per_block - 1) / rows_per_block;

    qk_rot_quant_kernel<<<blocks, threads>>>(qin, kin, qout, kout, nrows);
}

// round 2
// speedup vs baseline: 1.0710x; 1.0710x over previous
#include <cuda_runtime.h>

#define FULL_MASK 0xFFFFFFFFu

// In-warp 128-point FWHT on TWO independent rows simultaneously.
// Interleaving the two rows gives the scheduler independent work to
// cover the ~26-cycle SHFL latency of each butterfly stage.
__device__ __forceinline__ void fwht128_x2(float4& u, float4& v, int lane) {
    // ---- row u: in-register stages (index bits 0,1) ----
    {
        float a = u.x + u.y, b = u.x - u.y;
        float c = u.z + u.w, d = u.z - u.w;
        u.x = a + c; u.y = b + d; u.z = a - c; u.w = b - d;
    }
    // ---- row v: in-register stages ----
    {
        float a = v.x + v.y, b = v.x - v.y;
        float c = v.z + v.w, d = v.z - v.w;
        v.x = a + c; v.y = b + d; v.z = a - c; v.w = b - d;
    }
    // ---- cross-lane stages (index bits 2..6 = lane bits 0..4) ----
#pragma unroll
    for (int mask = 1; mask <= 16; mask <<= 1) {
        float ux = __shfl_xor_sync(FULL_MASK, u.x, mask);
        float uy = __shfl_xor_sync(FULL_MASK, u.y, mask);
        float uz = __shfl_xor_sync(FULL_MASK, u.z, mask);
        float uw = __shfl_xor_sync(FULL_MASK, u.w, mask);
        float vx = __shfl_xor_sync(FULL_MASK, v.x, mask);
        float vy = __shfl_xor_sync(FULL_MASK, v.y, mask);
        float vz = __shfl_xor_sync(FULL_MASK, v.z, mask);
        float vw = __shfl_xor_sync(FULL_MASK, v.w, mask);
        if (lane & mask) {
            u.x = ux - u.x; u.y = uy - u.y; u.z = uz - u.z; u.w = uw - u.w;
            v.x = vx - v.x; v.y = vy - v.y; v.z = vz - v.z; v.w = vw - v.w;
        } else {
            u.x += ux; u.y += uy; u.z += uz; u.w += uw;
            v.x += vx; v.y += vy; v.z += vz; v.w += vw;
        }
    }
}

__device__ __forceinline__ float4 scale4(float4 v, float s) {
    v.x *= s; v.y *= s; v.z *= s; v.w *= s;
    return v;
}

// 4-bit symmetric fake-quant of one (already rotated+scaled) k row.
__device__ __forceinline__ float4 quant4(float4 k) {
    float amax = fmaxf(fmaxf(fabsf(k.x), fabsf(k.y)),
                       fmaxf(fabsf(k.z), fabsf(k.w)));
#pragma unroll
    for (int mask = 16; mask >= 1; mask >>= 1)
        amax = fmaxf(amax, __shfl_xor_sync(FULL_MASK, amax, mask));
    if (amax == 0.0f) amax = 1.0f;
    const float qscale = amax / 7.0f;
    k.x = fminf(fmaxf(rintf(k.x / qscale), -8.0f), 7.0f) * qscale;
    k.y = fminf(fmaxf(rintf(k.y / qscale), -8.0f), 7.0f) * qscale;
    k.z = fminf(fmaxf(rintf(k.z / qscale), -8.0f), 7.0f) * qscale;
    k.w = fminf(fmaxf(rintf(k.w / qscale), -8.0f), 7.0f) * qscale;
    return k;
}

// One warp handles TWO row-indices: 2 q rows + 2 k rows.
// 4 independent float4 loads issued up-front (MLP=4/thread), then 4
// independent FWHT chains interleave to hide SHFL latency.
__global__ void __launch_bounds__(256)
qk_rot_quant_kernel(const float4* __restrict__ qin,
                    const float4* __restrict__ kin,
                    float4* __restrict__ qout,
                    float4* __restrict__ kout,
                    int nrow_pairs) {
    const int gwarp = (blockIdx.x * blockDim.x + threadIdx.x) >> 5;
    const int lane = threadIdx.x & 31;
    if (gwarp >= nrow_pairs) return;

    const float s = 0.088388347648318447f;  // 1/sqrt(128)
    const long long idx0 = (long long)gwarp * 64 + lane;  // row 2*gwarp
    const long long idx1 = idx0 + 32;                     // row 2*gwarp+1

    // issue all 4 loads before any compute
    float4 q0 = qin[idx0];
    float4 q1 = qin[idx1];
    float4 k0 = kin[idx0];
    float4 k1 = kin[idx1];

    // rotate q pair, store
    fwht128_x2(q0, q1, lane);
    qout[idx0] = scale4(q0, s);
    qout[idx1] = scale4(q1, s);

    // rotate k pair
    fwht128_x2(k0, k1, lane);
    k0 = scale4(k0, s);
    k1 = scale4(k1, s);

    // quantize + store
    kout[idx0] = quant4(k0);
    kout[idx1] = quant4(k1);
}

extern "C" void kernel_launch(void* const* d_in, const int* in_sizes, int n_in,
                              void* d_out, int out_size) {
    const float4* qin = (const float4*)d_in[0];
    const float4* kin = (const float4*)d_in[1];

    const int n_elems = in_sizes[0];        // 33554432
    const int nrows = n_elems / 128;        // 262144
    const int nrow_pairs = nrows / 2;       // 131072

    float4* qout = (float4*)d_out;
    float4* kout = (float4*)d_out + (size_t)n_elems / 4;

    const int threads = 256;                // 8 warps = 16 rows per block
    const int pairs_per_block = threads / 32;
    const int blocks = (nrow_pairs + pairs_per_block - 1) / pairs_per_block;

    qk_rot_quant_kernel<<<blocks, threads>>>(qin, kin, qout, kout, nrow_pairs);
}